// round 8
// baseline (speedup 1.0000x reference)
#include <cuda_runtime.h>
#include <cuda_bf16.h>
#include <cuda_fp16.h>
#include <math.h>
#include <stdint.h>

// Problem shapes (fixed by setup_inputs)
#define Bn   4096
#define Dn   1024
#define Kn   4096
#define EPSf 1e-6f
#define MARGINf 16.0f  // int8-quant d2 err (max ~9) + fp16 storage (~4) + headroom
#define QS   16.0f     // int8 quantization scale
#define QSI2 (1.0f / (QS * QS))   // 1/256

// Output layout (flatten+concat, float32):
#define OUT_LOC   0
#define OUT_LOSS  (2*Bn)
#define OUT_IDX   (2*Bn + 1)

typedef unsigned long long ull;

// ---------------- device scratch (no allocations allowed) ----------------
__device__ float         g_cb[Bn];
__device__ float         g_cw[Kn];
__device__ ull           g_packed[Bn];
__device__ signed char   g_xq[Bn * Dn];              // s8 x       [B][D]
__device__ signed char   g_wtq[Kn * Dn];             // s8 W^T     [K][D]
__device__ float         g_wt32[Kn * Dn];            // fp32 W^T   [K][D]
__device__ __half        g_approxh[(size_t)Bn * Kn]; // fp16 approx d2 [B][K]

// ---------------- PTX helpers ----------------
__device__ __forceinline__ uint32_t smem_u32(const void* p) {
    return (uint32_t)__cvta_generic_to_shared(p);
}
__device__ __forceinline__ void cp_async16(uint32_t dst, const void* src) {
    asm volatile("cp.async.cg.shared.global [%0], [%1], 16;" :: "r"(dst), "l"(src));
}
__device__ __forceinline__ void cp_commit() {
    asm volatile("cp.async.commit_group;" ::: "memory");
}
template <int N> __device__ __forceinline__ void cp_wait_group() {
    asm volatile("cp.async.wait_group %0;" :: "n"(N) : "memory");
}
__device__ __forceinline__ void ldsm4(uint32_t (&r)[4], uint32_t addr) {
    asm volatile("ldmatrix.sync.aligned.m8n8.x4.shared.b16 {%0,%1,%2,%3}, [%4];"
        : "=r"(r[0]), "=r"(r[1]), "=r"(r[2]), "=r"(r[3]) : "r"(addr));
}
// int8 IMMA, k=32: fragment byte-layout identical to e4m3 k32 / bf16 k16 plumbing
__device__ __forceinline__ void mma16832i(int (&d)[4], const uint32_t (&a)[4],
                                          uint32_t b0, uint32_t b1) {
    asm volatile(
        "mma.sync.aligned.m16n8k32.row.col.s32.s8.s8.s32 "
        "{%0,%1,%2,%3}, {%4,%5,%6,%7}, {%8,%9}, {%0,%1,%2,%3};"
        : "+r"(d[0]), "+r"(d[1]), "+r"(d[2]), "+r"(d[3])
        : "r"(a[0]), "r"(a[1]), "r"(a[2]), "r"(a[3]), "r"(b0), "r"(b1));
}
__device__ __forceinline__ int q8(float v) {
    int q = __float2int_rn(v * QS);
    return max(-127, min(127, q));
}

// ================= prep (1 launch) ====
// roles by blockIdx.x:
//   [0, 4096)      conv_x (s8) + row_stats (block b == row b)
//   [4096, 8192)   conv_wt  : W -> W^T (s8 + fp32), 32x32 tiles
//   [8192, 8320)   col_stats: g_cw (block owns 32 cols)
//   [8320, 8336)   init     : g_packed, loss
#define PREP_BLOCKS 8336

__global__ void prep_kernel(const float* __restrict__ x,
                            const float* __restrict__ w,
                            float* __restrict__ out) {
    __shared__ float tile[32][33];
    __shared__ float cs[2][8][32];
    const int b = blockIdx.x;
    const int t = threadIdx.x;

    if (b < 4096) {                                  // ---- conv_x + row_stats
        int i = b * 256 + t;                         // float4 index; block b == row b
        float4 v = reinterpret_cast<const float4*>(x)[i];
        uint32_t pk = (uint32_t)(q8(v.x) & 0xFF)
                    | ((uint32_t)(q8(v.y) & 0xFF) << 8)
                    | ((uint32_t)(q8(v.z) & 0xFF) << 16)
                    | ((uint32_t)(q8(v.w) & 0xFF) << 24);
        reinterpret_cast<uint32_t*>(g_xq)[i] = pk;
        float s  = v.x + v.y + v.z + v.w;
        float s2 = v.x * v.x + v.y * v.y + v.z * v.z + v.w * v.w;
#pragma unroll
        for (int off = 16; off; off >>= 1) {
            s  += __shfl_down_sync(0xFFFFFFFFu, s,  off);
            s2 += __shfl_down_sync(0xFFFFFFFFu, s2, off);
        }
        if ((t & 31) == 0) { cs[0][t >> 5][0] = s; cs[1][t >> 5][0] = s2; }
        __syncthreads();
        if (t == 0) {
            float ss = 0.0f, ss2 = 0.0f;
#pragma unroll
            for (int j = 0; j < 8; j++) { ss += cs[0][j][0]; ss2 += cs[1][j][0]; }
            g_cb[b] = ss2 + 2.0f * EPSf * ss + (float)Dn * EPSf * EPSf;
        }
    } else if (b < 8192) {                           // ---- conv_wt
        int bb = b - 4096;
        int n0 = (bb & 127) * 32;
        int d0 = (bb >> 7) * 32;
        int tx = t & 31, ty = t >> 5;                // 32 x 8
#pragma unroll
        for (int p = 0; p < 4; p++)
            tile[ty + p * 8][tx] = w[(size_t)(d0 + ty + p * 8) * Kn + n0 + tx];
        __syncthreads();
#pragma unroll
        for (int p = 0; p < 4; p++) {
            int n = n0 + ty + p * 8;
            int d = d0 + tx;
            float v = tile[tx][ty + p * 8];
            g_wt32[(size_t)n * Dn + d] = v;
            g_wtq[(size_t)n * Dn + d]  = (signed char)q8(v);
        }
    } else if (b < 8320) {                           // ---- col_stats + cw
        int k0 = (b - 8192) * 32;
        int kk = t & 31, seg = t >> 5;
        const float* p = w + (size_t)seg * 128 * Kn + k0 + kk;
        float s = 0.0f, s2 = 0.0f;
#pragma unroll 8
        for (int d = 0; d < 128; d++) {
            float v = p[(size_t)d * Kn];
            s += v; s2 += v * v;
        }
        cs[0][seg][kk] = s;
        cs[1][seg][kk] = s2;
        __syncthreads();
        if (t < 32) {
            float ssum = 0.0f, s2sum = 0.0f;
#pragma unroll
            for (int j = 0; j < 8; j++) { ssum += cs[0][j][t]; s2sum += cs[1][j][t]; }
            g_cw[k0 + t] = s2sum - 2.0f * EPSf * ssum;
        }
    } else {                                         // ---- init
        int i = (b - 8320) * 256 + t;
        g_packed[i] = ~0ull;
        if (i == 0) out[OUT_LOSS] = 0.0f;
    }
}

// ================= GEMM (mma.sync s8 IMMA) + d2 epilogue + rowwise min ====
// CTA tile 128x128, 8 warps = 4(M) x 2(N), warp tile 32x64.
// K per stage = 64 s8 elements (64 bytes/row); double buffer; NITER = 16.
#define BM 128
#define BN 128
#define BKB 64       // K elements (bytes) per stage
#define LDSB 80      // 64B data + 16B pad -> conflict-free ldmatrix
#define STAGE_BYTES (BM * LDSB)   // 10240
#define NITER (Dn / BKB)          // 16

__global__ __launch_bounds__(256, 2)
void gemm_mma_kernel() {
    __shared__ unsigned char As[2][STAGE_BYTES];
    __shared__ unsigned char Bs[2][STAGE_BYTES];
    __shared__ ull smin[BM];

    const int tid  = threadIdx.x;
    const int lane = tid & 31;
    const int wid  = tid >> 5;
    const int wm   = wid >> 1;          // 0..3 (M)
    const int wn   = wid & 1;           // 0..1 (N)
    const int bm0  = blockIdx.y * BM;
    const int bn0  = blockIdx.x * BN;

    for (int i = tid; i < BM; i += 256) smin[i] = ~0ull;

    int acc[2][4][2][4];
#pragma unroll
    for (int a = 0; a < 2; a++)
#pragma unroll
        for (int n = 0; n < 4; n++)
#pragma unroll
            for (int h = 0; h < 2; h++)
#pragma unroll
                for (int q = 0; q < 4; q++) acc[a][n][h][q] = 0;

    const uint32_t sA = smem_u32(As);
    const uint32_t sB = smem_u32(Bs);

    // cp.async mapping: 128 rows x 4 chunks(16B); thread -> (row=tid>>2, chunk=tid&3),
    // rows covered in 2 passes (+0, +64). Same for A and B.
    const int ldrow = tid >> 2;         // 0..63
    const int ldc   = tid & 3;          // 0..3
    const uint32_t dstA = sA + ldrow * LDSB + ldc * 16;
    const uint32_t dstB = sB + ldrow * LDSB + ldc * 16;
    const signed char* gA = g_xq  + (size_t)(bm0 + ldrow) * Dn + ldc * 16;
    const signed char* gB = g_wtq + (size_t)(bn0 + ldrow) * Dn + ldc * 16;

    auto load_stage = [&](int it, int buf) {
        const int d0 = it * BKB;
#pragma unroll
        for (int p = 0; p < 2; p++) {
            cp_async16(dstA + buf * STAGE_BYTES + p * (64 * LDSB),
                       gA + d0 + (size_t)(p * 64) * Dn);
            cp_async16(dstB + buf * STAGE_BYTES + p * (64 * LDSB),
                       gB + d0 + (size_t)(p * 64) * Dn);
        }
        cp_commit();
    };

    // ldmatrix lane mappings (byte-identical plumbing, verified R5/R7)
    const int lr16 = lane & 15;
    const int hc   = lane >> 4;                          // A: k-half (16B)
    const int boff = ((lane & 16) >> 1) + (lane & 7);    // B: n-row within 16
    const int bch  = (lane >> 3) & 1;                    // B: k-half (16B)

    auto compute_stage = [&](int buf) {
        const uint32_t a0 = sA + buf * STAGE_BYTES;
        const uint32_t b0 = sB + buf * STAGE_BYTES;
#pragma unroll
        for (int kk = 0; kk < 2; kk++) {                 // two k32 groups (32B each)
            uint32_t af[2][4];
#pragma unroll
            for (int mt = 0; mt < 2; mt++)
                ldsm4(af[mt], a0 + (wm * 32 + mt * 16 + lr16) * LDSB
                               + kk * 32 + hc * 16);
#pragma unroll
            for (int nt = 0; nt < 4; nt++) {
                uint32_t bf[4];
                ldsm4(bf, b0 + (wn * 64 + nt * 16 + boff) * LDSB
                           + kk * 32 + bch * 16);
#pragma unroll
                for (int mt = 0; mt < 2; mt++) {
                    mma16832i(acc[mt][nt][0], af[mt], bf[0], bf[1]);
                    mma16832i(acc[mt][nt][1], af[mt], bf[2], bf[3]);
                }
            }
        }
    };

    load_stage(0, 0);
    for (int it = 0; it < NITER; ++it) {
        const int buf = it & 1;
        if (it < NITER - 1) { load_stage(it + 1, buf ^ 1); cp_wait_group<1>(); }
        else                { cp_wait_group<0>(); }
        __syncthreads();
        compute_stage(buf);
        __syncthreads();
    }

    // ---- epilogue: d2 = cb + cw - 2*acc/QS^2; fp16 store; packed rowwise min
    const int lr = lane >> 2;   // 0..7
    const int lc = lane & 3;    // 0..3
#pragma unroll
    for (int mt = 0; mt < 2; mt++)
#pragma unroll
    for (int rp = 0; rp < 2; rp++) {
        const int r = bm0 + wm * 32 + mt * 16 + rp * 8 + lr;
        const float cbv = __ldg(&g_cb[r]);
        ull best = ~0ull;
        __half* orow = g_approxh + (size_t)r * Kn;
#pragma unroll
        for (int nt = 0; nt < 4; nt++)
#pragma unroll
        for (int h = 0; h < 2; h++) {
            const int c = bn0 + wn * 64 + nt * 16 + h * 8 + lc * 2;
            const float2 cw2 = *reinterpret_cast<const float2*>(&g_cw[c]);
            const float v0 = (float)acc[mt][nt][h][rp * 2 + 0] * QSI2;
            const float v1 = (float)acc[mt][nt][h][rp * 2 + 1] * QSI2;
            float dd0 = fmaxf(cbv + cw2.x - 2.0f * v0, 0.0f);
            float dd1 = fmaxf(cbv + cw2.y - 2.0f * v1, 0.0f);
            *reinterpret_cast<__half2*>(orow + c) = __floats2half2_rn(dd0, dd1);
            ull k0 = ((ull)__float_as_uint(dd0) << 32) | (unsigned)c;
            ull k1 = ((ull)__float_as_uint(dd1) << 32) | (unsigned)(c + 1);
            ull km = k0 < k1 ? k0 : k1;
            if (km < best) best = km;
        }
        ull o = __shfl_xor_sync(0xFFFFFFFFu, best, 1); if (o < best) best = o;
        o     = __shfl_xor_sync(0xFFFFFFFFu, best, 2); if (o < best) best = o;
        if (lc == 0) atomicMin(&smin[r - bm0], best);
    }
    __syncthreads();
    for (int i = tid; i < BM; i += 256)
        atomicMin(&g_packed[bm0 + i], smin[i]);
}

// ================= exact refine + outputs + loss (1 launch) ===============
__global__ void refine_finalize_kernel(const float* __restrict__ x,
                                       const float* __restrict__ loc,
                                       float* __restrict__ out) {
    const int b    = blockIdx.x * 8 + (threadIdx.x >> 5);
    const int lane = threadIdx.x & 31;

    const ull key0  = g_packed[b];
    const float amin = __uint_as_float((unsigned)(key0 >> 32));
    const float thr  = amin + MARGINf;
    const float cbv  = g_cb[b];
    const float4* xr = reinterpret_cast<const float4*>(x + (size_t)b * Dn);
    const __half2* arow2 =
        reinterpret_cast<const __half2*>(g_approxh + (size_t)b * Kn);

    ull best = ~0ull;
    for (int k0 = 0; k0 < Kn; k0 += 64) {
        __half2 h2 = arow2[(k0 >> 1) + lane];
        float a0 = __low2float(h2), a1 = __high2float(h2);
        unsigned m0 = __ballot_sync(0xFFFFFFFFu, a0 <= thr);
        unsigned m1 = __ballot_sync(0xFFFFFFFFu, a1 <= thr);
        while (m0 | m1) {
            int k;
            if (m0) { int j = __ffs(m0) - 1; m0 &= m0 - 1; k = k0 + 2 * j; }
            else    { int j = __ffs(m1) - 1; m1 &= m1 - 1; k = k0 + 2 * j + 1; }
            const float4* wr =
                reinterpret_cast<const float4*>(g_wt32 + (size_t)k * Dn);
            float s = 0.0f;
#pragma unroll
            for (int i = 0; i < 8; i++) {
                float4 xv = xr[lane + 32 * i];
                float4 wv = wr[lane + 32 * i];
                s += xv.x * wv.x + xv.y * wv.y + xv.z * wv.z + xv.w * wv.w;
            }
#pragma unroll
            for (int off = 16; off; off >>= 1)
                s += __shfl_xor_sync(0xFFFFFFFFu, s, off);
            float d2 = fmaxf(cbv + g_cw[k] - 2.0f * s, 0.0f);
            ull key = ((ull)__float_as_uint(d2) << 32) | (unsigned)k;
            if (key < best) best = key;
        }
    }

    __shared__ float sred[8];
    if (lane == 0) {
        unsigned idx = (unsigned)(best & 0xFFFFFFFFu);
        float d2 = __uint_as_float((unsigned)(best >> 32));
        float dist = sqrtf(d2);
        out[OUT_LOC + 2 * b + 0] = loc[2 * idx + 0];
        out[OUT_LOC + 2 * b + 1] = loc[2 * idx + 1];
        out[OUT_IDX + b]         = (float)idx;
        sred[threadIdx.x >> 5] = dist;
    }
    __syncthreads();
    if (threadIdx.x == 0) {
        float s = 0.0f;
#pragma unroll
        for (int i = 0; i < 8; i++) s += sred[i];
        atomicAdd(&out[OUT_LOSS], s * (1.0f / (float)Bn));
    }
}

// ---------------- launch ----------------
extern "C" void kernel_launch(void* const* d_in, const int* in_sizes, int n_in,
                              void* d_out, int out_size) {
    const float* x   = (const float*)d_in[0];  // [B, D]
    const float* w   = (const float*)d_in[1];  // [D, K]
    const float* loc = (const float*)d_in[2];  // [K, 2]
    float* out = (float*)d_out;

    prep_kernel<<<PREP_BLOCKS, 256>>>(x, w, out);
    gemm_mma_kernel<<<dim3(Kn / BN, Bn / BM), 256>>>();
    refine_finalize_kernel<<<Bn / 8, 256>>>(x, loc, out);
}

// round 9
// speedup vs baseline: 1.8710x; 1.8710x over previous
#include <cuda_runtime.h>
#include <cuda_bf16.h>
#include <cuda_fp16.h>
#include <math.h>
#include <stdint.h>

// Problem shapes (fixed by setup_inputs)
#define Bn   4096
#define Dn   1024
#define Kn   4096
#define EPSf 1e-6f
#define MARGINf 16.0f  // covers fp8 GEMM err (worst ~13) + fp16 storage err

// Output layout (flatten+concat, float32):
#define OUT_LOC   0
#define OUT_LOSS  (2*Bn)
#define OUT_IDX   (2*Bn + 1)

typedef unsigned long long ull;

// ---------------- device scratch (no allocations allowed) ----------------
__device__ float         g_cb[Bn];
__device__ float         g_cw[Kn];
__device__ ull           g_packed[Bn];
__device__ unsigned char g_xq[Bn * Dn];              // e4m3 x     [B][D]
__device__ unsigned char g_wtq[Kn * Dn];             // e4m3 W^T   [K][D]
__device__ float         g_wt32[Kn * Dn];            // fp32 W^T   [K][D]
__device__ __half        g_approxh[(size_t)Bn * Kn]; // fp16 approx d2 [B][K]

// ---------------- PTX helpers ----------------
__device__ __forceinline__ uint32_t smem_u32(const void* p) {
    return (uint32_t)__cvta_generic_to_shared(p);
}
__device__ __forceinline__ void cp_async16(uint32_t dst, const void* src) {
    asm volatile("cp.async.cg.shared.global [%0], [%1], 16;" :: "r"(dst), "l"(src));
}
__device__ __forceinline__ void cp_commit() {
    asm volatile("cp.async.commit_group;" ::: "memory");
}
template <int N> __device__ __forceinline__ void cp_wait_group() {
    asm volatile("cp.async.wait_group %0;" :: "n"(N) : "memory");
}
__device__ __forceinline__ void ldsm4(uint32_t (&r)[4], uint32_t addr) {
    asm volatile("ldmatrix.sync.aligned.m8n8.x4.shared.b16 {%0,%1,%2,%3}, [%4];"
        : "=r"(r[0]), "=r"(r[1]), "=r"(r[2]), "=r"(r[3]) : "r"(addr));
}
// fp8 e4m3 MMA, k=32
__device__ __forceinline__ void mma16832q(float (&d)[4], const uint32_t (&a)[4],
                                          uint32_t b0, uint32_t b1) {
    asm volatile(
        "mma.sync.aligned.m16n8k32.row.col.f32.e4m3.e4m3.f32 "
        "{%0,%1,%2,%3}, {%4,%5,%6,%7}, {%8,%9}, {%0,%1,%2,%3};"
        : "+f"(d[0]), "+f"(d[1]), "+f"(d[2]), "+f"(d[3])
        : "r"(a[0]), "r"(a[1]), "r"(a[2]), "r"(a[3]), "r"(b0), "r"(b1));
}
// pack 2 floats -> e4m3x2 (low byte = lo, high byte = hi)
__device__ __forceinline__ uint32_t f2_to_e4m3x2(float hi, float lo) {
    uint16_t r;
    asm("cvt.rn.satfinite.e4m3x2.f32 %0, %1, %2;" : "=h"(r) : "f"(hi), "f"(lo));
    return (uint32_t)r;
}

// ================= prep (1 launch) ====
// roles by blockIdx.x:
//   [0, 1024)      conv_x + row_stats   (block covers 4 rows)
//   [1024, 3072)   conv_wt: 32(d) x 64(n) tiles -> W^T fp8 + fp32
//   [3072, 3136)   col_stats: g_cw (block owns 64 cols)
//   [3136, 3152)   init: g_packed, loss
#define PREP_BLOCKS 3152

__global__ void prep_kernel(const float* __restrict__ x,
                            const float* __restrict__ w,
                            float* __restrict__ out) {
    __shared__ float tile[32][65];
    __shared__ float cs[2][8][64];
    const int b = blockIdx.x;
    const int t = threadIdx.x;

    if (b < 1024) {                                  // ---- conv_x + row_stats
        const int r = t >> 6;                        // 0..3 (row within block)
        const int c = t & 63;                        // chunk within row
        const int row = b * 4 + r;
        const float4* xr = reinterpret_cast<const float4*>(x) + (size_t)row * 256;
        uint32_t* xo = reinterpret_cast<uint32_t*>(g_xq) + (size_t)row * 256;
        float s = 0.0f, s2 = 0.0f;
#pragma unroll
        for (int j = 0; j < 4; j++) {
            float4 v = xr[c + j * 64];
            uint32_t lo = f2_to_e4m3x2(v.y, v.x);
            uint32_t hi = f2_to_e4m3x2(v.w, v.z);
            xo[c + j * 64] = lo | (hi << 16);
            s  += v.x + v.y + v.z + v.w;
            s2 += v.x * v.x + v.y * v.y + v.z * v.z + v.w * v.w;
        }
#pragma unroll
        for (int off = 16; off; off >>= 1) {
            s  += __shfl_down_sync(0xFFFFFFFFu, s,  off);
            s2 += __shfl_down_sync(0xFFFFFFFFu, s2, off);
        }
        if ((t & 31) == 0) { cs[0][t >> 5][0] = s; cs[1][t >> 5][0] = s2; }
        __syncthreads();
        if (t < 4) {
            float ss  = cs[0][2 * t][0] + cs[0][2 * t + 1][0];
            float ss2 = cs[1][2 * t][0] + cs[1][2 * t + 1][0];
            g_cb[b * 4 + t] = ss2 + 2.0f * EPSf * ss + (float)Dn * EPSf * EPSf;
        }
    } else if (b < 3072) {                           // ---- conv_wt (32d x 64n tile)
        const int bb = b - 1024;
        const int n0 = (bb & 63) * 64;
        const int d0 = (bb >> 6) * 32;
        const int tx = t & 63;                       // n within tile
        const int ty = t >> 6;                       // 0..3
#pragma unroll
        for (int p = 0; p < 8; p++) {
            int dl = ty + p * 4;                     // 0..31
            tile[dl][tx] = w[(size_t)(d0 + dl) * Kn + n0 + tx];
        }
        __syncthreads();
        {
            const int nl = t >> 2;                   // 0..63
            const int dq = (t & 3) * 8;              // 0,8,16,24
            float v[8];
#pragma unroll
            for (int j = 0; j < 8; j++) v[j] = tile[dq + j][nl];
            float* w32 = g_wt32 + (size_t)(n0 + nl) * Dn + d0 + dq;
            *reinterpret_cast<float4*>(w32 + 0) = make_float4(v[0], v[1], v[2], v[3]);
            *reinterpret_cast<float4*>(w32 + 4) = make_float4(v[4], v[5], v[6], v[7]);
            uint32_t q0 = f2_to_e4m3x2(v[1], v[0]) | (f2_to_e4m3x2(v[3], v[2]) << 16);
            uint32_t q1 = f2_to_e4m3x2(v[5], v[4]) | (f2_to_e4m3x2(v[7], v[6]) << 16);
            uint2 pk; pk.x = q0; pk.y = q1;
            *reinterpret_cast<uint2*>(g_wtq + (size_t)(n0 + nl) * Dn + d0 + dq) = pk;
        }
    } else if (b < 3136) {                           // ---- col_stats + cw
        const int k0 = (b - 3072) * 64;
        const int kk = t & 63, seg = t >> 6;         // 4 segs x 256 d
        const float* p = w + (size_t)seg * 256 * Kn + k0 + kk;
        float s = 0.0f, s2 = 0.0f;
#pragma unroll 8
        for (int d = 0; d < 256; d++) {
            float v = p[(size_t)d * Kn];
            s += v; s2 += v * v;
        }
        cs[0][seg][kk] = s;
        cs[1][seg][kk] = s2;
        __syncthreads();
        if (t < 64) {
            float ssum = 0.0f, s2sum = 0.0f;
#pragma unroll
            for (int j = 0; j < 4; j++) { ssum += cs[0][j][t]; s2sum += cs[1][j][t]; }
            g_cw[k0 + t] = s2sum - 2.0f * EPSf * ssum;
        }
    } else {                                         // ---- init
        int i = (b - 3136) * 256 + t;
        g_packed[i] = ~0ull;
        if (i == 0) out[OUT_LOSS] = 0.0f;
    }
}

// ================= GEMM (mma.sync fp8 e4m3) + d2 epilogue + rowwise min ===
// R7 config (best measured): CTA 128x128, 8 warps = 4(M) x 2(N), warp tile 32x64.
#define BM 128
#define BN 128
#define BKB 64       // K elements (bytes) per stage
#define LDSB 80      // 64B data + 16B pad -> conflict-free ldmatrix
#define STAGE_BYTES (BM * LDSB)   // 10240
#define NITER (Dn / BKB)          // 16

__global__ __launch_bounds__(256, 2)
void gemm_mma_kernel() {
    __shared__ unsigned char As[2][STAGE_BYTES];
    __shared__ unsigned char Bs[2][STAGE_BYTES];
    __shared__ ull smin[BM];

    const int tid  = threadIdx.x;
    const int lane = tid & 31;
    const int wid  = tid >> 5;
    const int wm   = wid >> 1;          // 0..3 (M)
    const int wn   = wid & 1;           // 0..1 (N)
    const int bm0  = blockIdx.y * BM;
    const int bn0  = blockIdx.x * BN;

    for (int i = tid; i < BM; i += 256) smin[i] = ~0ull;

    float acc[2][4][2][4];
#pragma unroll
    for (int a = 0; a < 2; a++)
#pragma unroll
        for (int n = 0; n < 4; n++)
#pragma unroll
            for (int h = 0; h < 2; h++)
#pragma unroll
                for (int q = 0; q < 4; q++) acc[a][n][h][q] = 0.0f;

    const uint32_t sA = smem_u32(As);
    const uint32_t sB = smem_u32(Bs);

    const int ldrow = tid >> 2;         // 0..63
    const int ldc   = tid & 3;          // 0..3
    const uint32_t dstA = sA + ldrow * LDSB + ldc * 16;
    const uint32_t dstB = sB + ldrow * LDSB + ldc * 16;
    const unsigned char* gA = g_xq  + (size_t)(bm0 + ldrow) * Dn + ldc * 16;
    const unsigned char* gB = g_wtq + (size_t)(bn0 + ldrow) * Dn + ldc * 16;

    auto load_stage = [&](int it, int buf) {
        const int d0 = it * BKB;
#pragma unroll
        for (int p = 0; p < 2; p++) {
            cp_async16(dstA + buf * STAGE_BYTES + p * (64 * LDSB),
                       gA + d0 + (size_t)(p * 64) * Dn);
            cp_async16(dstB + buf * STAGE_BYTES + p * (64 * LDSB),
                       gB + d0 + (size_t)(p * 64) * Dn);
        }
        cp_commit();
    };

    const int lr16 = lane & 15;
    const int hc   = lane >> 4;                          // A: k-half (16B)
    const int boff = ((lane & 16) >> 1) + (lane & 7);    // B: n-row within 16
    const int bch  = (lane >> 3) & 1;                    // B: k-half (16B)

    auto compute_stage = [&](int buf) {
        const uint32_t a0 = sA + buf * STAGE_BYTES;
        const uint32_t b0 = sB + buf * STAGE_BYTES;
#pragma unroll
        for (int kk = 0; kk < 2; kk++) {                 // two k32 groups
            uint32_t af[2][4];
#pragma unroll
            for (int mt = 0; mt < 2; mt++)
                ldsm4(af[mt], a0 + (wm * 32 + mt * 16 + lr16) * LDSB
                               + kk * 32 + hc * 16);
#pragma unroll
            for (int nt = 0; nt < 4; nt++) {
                uint32_t bf[4];
                ldsm4(bf, b0 + (wn * 64 + nt * 16 + boff) * LDSB
                           + kk * 32 + bch * 16);
#pragma unroll
                for (int mt = 0; mt < 2; mt++) {
                    mma16832q(acc[mt][nt][0], af[mt], bf[0], bf[1]);
                    mma16832q(acc[mt][nt][1], af[mt], bf[2], bf[3]);
                }
            }
        }
    };

    load_stage(0, 0);
    for (int it = 0; it < NITER; ++it) {
        const int buf = it & 1;
        if (it < NITER - 1) { load_stage(it + 1, buf ^ 1); cp_wait_group<1>(); }
        else                { cp_wait_group<0>(); }
        __syncthreads();
        compute_stage(buf);
        __syncthreads();
    }

    // ---- epilogue: d2 = cb + cw - 2*acc; fp16 store; packed rowwise min ----
    const int lr = lane >> 2;   // 0..7
    const int lc = lane & 3;    // 0..3
#pragma unroll
    for (int mt = 0; mt < 2; mt++)
#pragma unroll
    for (int rp = 0; rp < 2; rp++) {
        const int r = bm0 + wm * 32 + mt * 16 + rp * 8 + lr;
        const float cbv = __ldg(&g_cb[r]);
        ull best = ~0ull;
        __half* orow = g_approxh + (size_t)r * Kn;
#pragma unroll
        for (int nt = 0; nt < 4; nt++)
#pragma unroll
        for (int h = 0; h < 2; h++) {
            const int c = bn0 + wn * 64 + nt * 16 + h * 8 + lc * 2;
            const float2 cw2 = *reinterpret_cast<const float2*>(&g_cw[c]);
            const float v0 = acc[mt][nt][h][rp * 2 + 0];
            const float v1 = acc[mt][nt][h][rp * 2 + 1];
            float dd0 = fmaxf(cbv + cw2.x - 2.0f * v0, 0.0f);
            float dd1 = fmaxf(cbv + cw2.y - 2.0f * v1, 0.0f);
            *reinterpret_cast<__half2*>(orow + c) = __floats2half2_rn(dd0, dd1);
            ull k0 = ((ull)__float_as_uint(dd0) << 32) | (unsigned)c;
            ull k1 = ((ull)__float_as_uint(dd1) << 32) | (unsigned)(c + 1);
            ull km = k0 < k1 ? k0 : k1;
            if (km < best) best = km;
        }
        ull o = __shfl_xor_sync(0xFFFFFFFFu, best, 1); if (o < best) best = o;
        o     = __shfl_xor_sync(0xFFFFFFFFu, best, 2); if (o < best) best = o;
        if (lc == 0) atomicMin(&smin[r - bm0], best);
    }
    __syncthreads();
    for (int i = tid; i < BM; i += 256)
        atomicMin(&g_packed[bm0 + i], smin[i]);
}

// ================= exact refine + outputs + loss (1 launch) ===============
__global__ void refine_finalize_kernel(const float* __restrict__ x,
                                       const float* __restrict__ loc,
                                       float* __restrict__ out) {
    const int b    = blockIdx.x * 8 + (threadIdx.x >> 5);
    const int lane = threadIdx.x & 31;

    const ull key0   = g_packed[b];
    const float amin = __uint_as_float((unsigned)(key0 >> 32));
    const float thr  = amin + MARGINf;
    const float cbv  = g_cb[b];
    const float4* xr = reinterpret_cast<const float4*>(x + (size_t)b * Dn);
    const float4* arow4 =
        reinterpret_cast<const float4*>(g_approxh + (size_t)b * Kn);

    ull best = ~0ull;
    for (int k0 = 0; k0 < Kn; k0 += 256) {               // 256 cols per iter
        float4 pk = arow4[(k0 >> 3) + lane];             // 8 halves
        const __half2* hp = reinterpret_cast<const __half2*>(&pk);
#pragma unroll
        for (int q = 0; q < 4; q++) {
            float a0 = __low2float(hp[q]), a1 = __high2float(hp[q]);
            unsigned m0 = __ballot_sync(0xFFFFFFFFu, a0 <= thr);
            unsigned m1 = __ballot_sync(0xFFFFFFFFu, a1 <= thr);
            while (m0 | m1) {
                int k;
                if (m0) { int j = __ffs(m0) - 1; m0 &= m0 - 1; k = k0 + 8 * j + 2 * q; }
                else    { int j = __ffs(m1) - 1; m1 &= m1 - 1; k = k0 + 8 * j + 2 * q + 1; }
                const float4* wr =
                    reinterpret_cast<const float4*>(g_wt32 + (size_t)k * Dn);
                float s = 0.0f;
#pragma unroll
                for (int i = 0; i < 8; i++) {
                    float4 xv = xr[lane + 32 * i];
                    float4 wv = wr[lane + 32 * i];
                    s += xv.x * wv.x + xv.y * wv.y + xv.z * wv.z + xv.w * wv.w;
                }
#pragma unroll
                for (int off = 16; off; off >>= 1)
                    s += __shfl_xor_sync(0xFFFFFFFFu, s, off);
                float d2 = fmaxf(cbv + g_cw[k] - 2.0f * s, 0.0f);
                ull key = ((ull)__float_as_uint(d2) << 32) | (unsigned)k;
                if (key < best) best = key;
            }
        }
    }

    __shared__ float sred[8];
    if (lane == 0) {
        unsigned idx = (unsigned)(best & 0xFFFFFFFFu);
        float d2 = __uint_as_float((unsigned)(best >> 32));
        float dist = sqrtf(d2);
        out[OUT_LOC + 2 * b + 0] = loc[2 * idx + 0];
        out[OUT_LOC + 2 * b + 1] = loc[2 * idx + 1];
        out[OUT_IDX + b]         = (float)idx;
        sred[threadIdx.x >> 5] = dist;
    }
    __syncthreads();
    if (threadIdx.x == 0) {
        float s = 0.0f;
#pragma unroll
        for (int i = 0; i < 8; i++) s += sred[i];
        atomicAdd(&out[OUT_LOSS], s * (1.0f / (float)Bn));
    }
}

// ---------------- launch ----------------
extern "C" void kernel_launch(void* const* d_in, const int* in_sizes, int n_in,
                              void* d_out, int out_size) {
    const float* x   = (const float*)d_in[0];  // [B, D]
    const float* w   = (const float*)d_in[1];  // [D, K]
    const float* loc = (const float*)d_in[2];  // [K, 2]
    float* out = (float*)d_out;

    prep_kernel<<<PREP_BLOCKS, 256>>>(x, w, out);
    gemm_mma_kernel<<<dim3(Kn / BN, Bn / BM), 256>>>();
    refine_finalize_kernel<<<Bn / 8, 256>>>(x, loc, out);
}

// round 12
// speedup vs baseline: 1.9133x; 1.0226x over previous
#include <cuda_runtime.h>
#include <cuda_bf16.h>
#include <cuda_fp16.h>
#include <math.h>
#include <stdint.h>

// Problem shapes (fixed by setup_inputs)
#define Bn   4096
#define Dn   1024
#define Kn   4096
#define EPSf 1e-6f
#define MARGINf 16.0f  // covers fp8 GEMM err (worst ~13) + fp16 storage err

// Output layout (flatten+concat, float32):
#define OUT_LOC   0
#define OUT_LOSS  (2*Bn)
#define OUT_IDX   (2*Bn + 1)

typedef unsigned long long ull;

// ---------------- device scratch (no allocations allowed) ----------------
__device__ float         g_cb[Bn];
__device__ float         g_cw[Kn];
__device__ ull           g_packed[Bn];
__device__ unsigned char g_xq[Bn * Dn];              // e4m3 x     [B][D]
__device__ unsigned char g_wtq[Kn * Dn];             // e4m3 W^T   [K][D]
__device__ float         g_wt32[Kn * Dn];            // fp32 W^T   [K][D]
__device__ __half        g_approxh[(size_t)Bn * Kn]; // fp16 approx d2 [B][K]

// ---------------- PTX helpers ----------------
__device__ __forceinline__ uint32_t smem_u32(const void* p) {
    return (uint32_t)__cvta_generic_to_shared(p);
}
__device__ __forceinline__ void cp_async16(uint32_t dst, const void* src) {
    asm volatile("cp.async.cg.shared.global [%0], [%1], 16;" :: "r"(dst), "l"(src));
}
__device__ __forceinline__ void cp_commit() {
    asm volatile("cp.async.commit_group;" ::: "memory");
}
template <int N> __device__ __forceinline__ void cp_wait_group() {
    asm volatile("cp.async.wait_group %0;" :: "n"(N) : "memory");
}
__device__ __forceinline__ void ldsm4(uint32_t (&r)[4], uint32_t addr) {
    asm volatile("ldmatrix.sync.aligned.m8n8.x4.shared.b16 {%0,%1,%2,%3}, [%4];"
        : "=r"(r[0]), "=r"(r[1]), "=r"(r[2]), "=r"(r[3]) : "r"(addr));
}
// fp8 e4m3 MMA, k=32
__device__ __forceinline__ void mma16832q(float (&d)[4], const uint32_t (&a)[4],
                                          uint32_t b0, uint32_t b1) {
    asm volatile(
        "mma.sync.aligned.m16n8k32.row.col.f32.e4m3.e4m3.f32 "
        "{%0,%1,%2,%3}, {%4,%5,%6,%7}, {%8,%9}, {%0,%1,%2,%3};"
        : "+f"(d[0]), "+f"(d[1]), "+f"(d[2]), "+f"(d[3])
        : "r"(a[0]), "r"(a[1]), "r"(a[2]), "r"(a[3]), "r"(b0), "r"(b1));
}
// pack 2 floats -> e4m3x2 (low byte = lo, high byte = hi)
__device__ __forceinline__ uint32_t f2_to_e4m3x2(float hi, float lo) {
    uint16_t r;
    asm("cvt.rn.satfinite.e4m3x2.f32 %0, %1, %2;" : "=h"(r) : "f"(hi), "f"(lo));
    return (uint32_t)r;
}

// ================= prep (1 launch; R7 role split, measured 18.7us) ====
// roles by blockIdx.x:
//   [0, 4096)      conv_x (fp8) + row_stats (block b == row b)
//   [4096, 8192)   conv_wt  : W -> W^T (fp8 + fp32), 32x32 tiles
//   [8192, 8320)   col_stats: g_cw (block owns 32 cols, 8x128-d segments)
//   [8320, 8336)   init     : g_packed, loss
#define PREP_BLOCKS 8336

__global__ void prep_kernel(const float* __restrict__ x,
                            const float* __restrict__ w,
                            float* __restrict__ out) {
    __shared__ float tile[32][33];
    __shared__ float cs[2][8][32];
    const int b = blockIdx.x;
    const int t = threadIdx.x;

    if (b < 4096) {                                  // ---- conv_x + row_stats
        int i = b * 256 + t;                         // float4 index; block b == row b
        float4 v = reinterpret_cast<const float4*>(x)[i];
        uint32_t lo = f2_to_e4m3x2(v.y, v.x);
        uint32_t hi = f2_to_e4m3x2(v.w, v.z);
        reinterpret_cast<uint32_t*>(g_xq)[i] = lo | (hi << 16);
        float s  = v.x + v.y + v.z + v.w;
        float s2 = v.x * v.x + v.y * v.y + v.z * v.z + v.w * v.w;
#pragma unroll
        for (int off = 16; off; off >>= 1) {
            s  += __shfl_down_sync(0xFFFFFFFFu, s,  off);
            s2 += __shfl_down_sync(0xFFFFFFFFu, s2, off);
        }
        if ((t & 31) == 0) { cs[0][t >> 5][0] = s; cs[1][t >> 5][0] = s2; }
        __syncthreads();
        if (t == 0) {
            float ss = 0.0f, ss2 = 0.0f;
#pragma unroll
            for (int j = 0; j < 8; j++) { ss += cs[0][j][0]; ss2 += cs[1][j][0]; }
            g_cb[b] = ss2 + 2.0f * EPSf * ss + (float)Dn * EPSf * EPSf;
        }
    } else if (b < 8192) {                           // ---- conv_wt
        int bb = b - 4096;
        int n0 = (bb & 127) * 32;
        int d0 = (bb >> 7) * 32;
        int tx = t & 31, ty = t >> 5;                // 32 x 8
#pragma unroll
        for (int p = 0; p < 4; p++)
            tile[ty + p * 8][tx] = w[(size_t)(d0 + ty + p * 8) * Kn + n0 + tx];
        __syncthreads();
#pragma unroll
        for (int p = 0; p < 4; p++) {
            int n = n0 + ty + p * 8;
            int d = d0 + tx;
            float v = tile[tx][ty + p * 8];
            g_wt32[(size_t)n * Dn + d] = v;
            uint32_t q = f2_to_e4m3x2(0.0f, v);      // low byte = e4m3(v)
            g_wtq[(size_t)n * Dn + d] = (unsigned char)(q & 0xFF);
        }
    } else if (b < 8320) {                           // ---- col_stats + cw
        int k0 = (b - 8192) * 32;
        int kk = t & 31, seg = t >> 5;
        const float* p = w + (size_t)seg * 128 * Kn + k0 + kk;
        float s = 0.0f, s2 = 0.0f;
#pragma unroll 8
        for (int d = 0; d < 128; d++) {
            float v = p[(size_t)d * Kn];
            s += v; s2 += v * v;
        }
        cs[0][seg][kk] = s;
        cs[1][seg][kk] = s2;
        __syncthreads();
        if (t < 32) {
            float ssum = 0.0f, s2sum = 0.0f;
#pragma unroll
            for (int j = 0; j < 8; j++) { ssum += cs[0][j][t]; s2sum += cs[1][j][t]; }
            g_cw[k0 + t] = s2sum - 2.0f * EPSf * ssum;
        }
    } else {                                         // ---- init
        int i = (b - 8320) * 256 + t;
        g_packed[i] = ~0ull;
        if (i == 0) out[OUT_LOSS] = 0.0f;
    }
}

// ================= GEMM (mma.sync fp8 e4m3) + d2 epilogue + rowwise min ===
// R7 config (best measured): CTA 128x128, 8 warps = 4(M) x 2(N), warp tile 32x64.
#define BM 128
#define BN 128
#define BKB 64       // K elements (bytes) per stage
#define LDSB 80      // 64B data + 16B pad -> conflict-free ldmatrix
#define STAGE_BYTES (BM * LDSB)   // 10240
#define NITER (Dn / BKB)          // 16

__global__ __launch_bounds__(256, 2)
void gemm_mma_kernel() {
    __shared__ unsigned char As[2][STAGE_BYTES];
    __shared__ unsigned char Bs[2][STAGE_BYTES];
    __shared__ ull smin[BM];

    const int tid  = threadIdx.x;
    const int lane = tid & 31;
    const int wid  = tid >> 5;
    const int wm   = wid >> 1;          // 0..3 (M)
    const int wn   = wid & 1;           // 0..1 (N)
    const int bm0  = blockIdx.y * BM;
    const int bn0  = blockIdx.x * BN;

    for (int i = tid; i < BM; i += 256) smin[i] = ~0ull;

    float acc[2][4][2][4];
#pragma unroll
    for (int a = 0; a < 2; a++)
#pragma unroll
        for (int n = 0; n < 4; n++)
#pragma unroll
            for (int h = 0; h < 2; h++)
#pragma unroll
                for (int q = 0; q < 4; q++) acc[a][n][h][q] = 0.0f;

    const uint32_t sA = smem_u32(As);
    const uint32_t sB = smem_u32(Bs);

    const int ldrow = tid >> 2;         // 0..63
    const int ldc   = tid & 3;          // 0..3
    const uint32_t dstA = sA + ldrow * LDSB + ldc * 16;
    const uint32_t dstB = sB + ldrow * LDSB + ldc * 16;
    const unsigned char* gA = g_xq  + (size_t)(bm0 + ldrow) * Dn + ldc * 16;
    const unsigned char* gB = g_wtq + (size_t)(bn0 + ldrow) * Dn + ldc * 16;

    auto load_stage = [&](int it, int buf) {
        const int d0 = it * BKB;
#pragma unroll
        for (int p = 0; p < 2; p++) {
            cp_async16(dstA + buf * STAGE_BYTES + p * (64 * LDSB),
                       gA + d0 + (size_t)(p * 64) * Dn);
            cp_async16(dstB + buf * STAGE_BYTES + p * (64 * LDSB),
                       gB + d0 + (size_t)(p * 64) * Dn);
        }
        cp_commit();
    };

    const int lr16 = lane & 15;
    const int hc   = lane >> 4;                          // A: k-half (16B)
    const int boff = ((lane & 16) >> 1) + (lane & 7);    // B: n-row within 16
    const int bch  = (lane >> 3) & 1;                    // B: k-half (16B)

    auto compute_stage = [&](int buf) {
        const uint32_t a0 = sA + buf * STAGE_BYTES;
        const uint32_t b0 = sB + buf * STAGE_BYTES;
#pragma unroll
        for (int kk = 0; kk < 2; kk++) {                 // two k32 groups
            uint32_t af[2][4];
#pragma unroll
            for (int mt = 0; mt < 2; mt++)
                ldsm4(af[mt], a0 + (wm * 32 + mt * 16 + lr16) * LDSB
                               + kk * 32 + hc * 16);
#pragma unroll
            for (int nt = 0; nt < 4; nt++) {
                uint32_t bf[4];
                ldsm4(bf, b0 + (wn * 64 + nt * 16 + boff) * LDSB
                           + kk * 32 + bch * 16);
#pragma unroll
                for (int mt = 0; mt < 2; mt++) {
                    mma16832q(acc[mt][nt][0], af[mt], bf[0], bf[1]);
                    mma16832q(acc[mt][nt][1], af[mt], bf[2], bf[3]);
                }
            }
        }
    };

    load_stage(0, 0);
    for (int it = 0; it < NITER; ++it) {
        const int buf = it & 1;
        if (it < NITER - 1) { load_stage(it + 1, buf ^ 1); cp_wait_group<1>(); }
        else                { cp_wait_group<0>(); }
        __syncthreads();
        compute_stage(buf);
        __syncthreads();
    }

    // ---- epilogue: d2 = cb + cw - 2*acc; fp16 store; packed rowwise min ----
    const int lr = lane >> 2;   // 0..7
    const int lc = lane & 3;    // 0..3
#pragma unroll
    for (int mt = 0; mt < 2; mt++)
#pragma unroll
    for (int rp = 0; rp < 2; rp++) {
        const int r = bm0 + wm * 32 + mt * 16 + rp * 8 + lr;
        const float cbv = __ldg(&g_cb[r]);
        ull best = ~0ull;
        __half* orow = g_approxh + (size_t)r * Kn;
#pragma unroll
        for (int nt = 0; nt < 4; nt++)
#pragma unroll
        for (int h = 0; h < 2; h++) {
            const int c = bn0 + wn * 64 + nt * 16 + h * 8 + lc * 2;
            const float2 cw2 = *reinterpret_cast<const float2*>(&g_cw[c]);
            const float v0 = acc[mt][nt][h][rp * 2 + 0];
            const float v1 = acc[mt][nt][h][rp * 2 + 1];
            float dd0 = fmaxf(cbv + cw2.x - 2.0f * v0, 0.0f);
            float dd1 = fmaxf(cbv + cw2.y - 2.0f * v1, 0.0f);
            *reinterpret_cast<__half2*>(orow + c) = __floats2half2_rn(dd0, dd1);
            ull k0 = ((ull)__float_as_uint(dd0) << 32) | (unsigned)c;
            ull k1 = ((ull)__float_as_uint(dd1) << 32) | (unsigned)(c + 1);
            ull km = k0 < k1 ? k0 : k1;
            if (km < best) best = km;
        }
        ull o = __shfl_xor_sync(0xFFFFFFFFu, best, 1); if (o < best) best = o;
        o     = __shfl_xor_sync(0xFFFFFFFFu, best, 2); if (o < best) best = o;
        if (lc == 0) atomicMin(&smin[r - bm0], best);
    }
    __syncthreads();
    for (int i = tid; i < BM; i += 256)
        atomicMin(&g_packed[bm0 + i], smin[i]);
}

// ================= exact refine + outputs + loss (1 launch) ===============
__global__ void refine_finalize_kernel(const float* __restrict__ x,
                                       const float* __restrict__ loc,
                                       float* __restrict__ out) {
    const int b    = blockIdx.x * 8 + (threadIdx.x >> 5);
    const int lane = threadIdx.x & 31;

    const ull key0   = g_packed[b];
    const float amin = __uint_as_float((unsigned)(key0 >> 32));
    const float thr  = amin + MARGINf;
    const float cbv  = g_cb[b];
    const float4* xr = reinterpret_cast<const float4*>(x + (size_t)b * Dn);
    const float4* arow4 =
        reinterpret_cast<const float4*>(g_approxh + (size_t)b * Kn);

    ull best = ~0ull;
    for (int k0 = 0; k0 < Kn; k0 += 256) {               // 256 cols per iter
        float4 pk = arow4[(k0 >> 3) + lane];             // 8 halves
        const __half2* hp = reinterpret_cast<const __half2*>(&pk);
#pragma unroll
        for (int q = 0; q < 4; q++) {
            float a0 = __low2float(hp[q]), a1 = __high2float(hp[q]);
            unsigned m0 = __ballot_sync(0xFFFFFFFFu, a0 <= thr);
            unsigned m1 = __ballot_sync(0xFFFFFFFFu, a1 <= thr);
            while (m0 | m1) {
                int k;
                if (m0) { int j = __ffs(m0) - 1; m0 &= m0 - 1; k = k0 + 8 * j + 2 * q; }
                else    { int j = __ffs(m1) - 1; m1 &= m1 - 1; k = k0 + 8 * j + 2 * q + 1; }
                const float4* wr =
                    reinterpret_cast<const float4*>(g_wt32 + (size_t)k * Dn);
                float s = 0.0f;
#pragma unroll
                for (int i = 0; i < 8; i++) {
                    float4 xv = xr[lane + 32 * i];
                    float4 wv = wr[lane + 32 * i];
                    s += xv.x * wv.x + xv.y * wv.y + xv.z * wv.z + xv.w * wv.w;
                }
#pragma unroll
                for (int off = 16; off; off >>= 1)
                    s += __shfl_xor_sync(0xFFFFFFFFu, s, off);
                float d2 = fmaxf(cbv + g_cw[k] - 2.0f * s, 0.0f);
                ull key = ((ull)__float_as_uint(d2) << 32) | (unsigned)k;
                if (key < best) best = key;
            }
        }
    }

    __shared__ float sred[8];
    if (lane == 0) {
        unsigned idx = (unsigned)(best & 0xFFFFFFFFu);
        float d2 = __uint_as_float((unsigned)(best >> 32));
        float dist = sqrtf(d2);
        out[OUT_LOC + 2 * b + 0] = loc[2 * idx + 0];
        out[OUT_LOC + 2 * b + 1] = loc[2 * idx + 1];
        out[OUT_IDX + b]         = (float)idx;
        sred[threadIdx.x >> 5] = dist;
    }
    __syncthreads();
    if (threadIdx.x == 0) {
        float s = 0.0f;
#pragma unroll
        for (int i = 0; i < 8; i++) s += sred[i];
        atomicAdd(&out[OUT_LOSS], s * (1.0f / (float)Bn));
    }
}

// ---------------- launch ----------------
extern "C" void kernel_launch(void* const* d_in, const int* in_sizes, int n_in,
                              void* d_out, int out_size) {
    const float* x   = (const float*)d_in[0];  // [B, D]
    const float* w   = (const float*)d_in[1];  // [D, K]
    const float* loc = (const float*)d_in[2];  // [K, 2]
    float* out = (float*)d_out;

    prep_kernel<<<PREP_BLOCKS, 256>>>(x, w, out);
    gemm_mma_kernel<<<dim3(Kn / BN, Bn / BM), 256>>>();
    refine_finalize_kernel<<<Bn / 8, 256>>>(x, loc, out);
}